// round 9
// baseline (speedup 1.0000x reference)
#include <cuda_runtime.h>
#include <cuda_fp16.h>

#define Bn 8
#define Hn 192
#define Wn 192
#define Sn 4
#define Cn 32

// Stream-A scratch (w=18, w=1) / Stream-B scratch (w=8, w=3), half2-packed chains.
__device__ __half2 g_A1[11206656 + 262144];   // w18 s1/s3: 228*192*256
__device__ __half2 g_A2[13307904 + 262144];   // w18 s2: 228*228*256
__device__ __half2 g_B1[10223616 + 262144];   // w8 s1/s3: 208*192*256
__device__ __half2 g_B2[11075584 + 262144];   // w8 s2: 208*208*256

template<int WID> struct SP;
template<> struct SP<1>  { static constexpr int SI = 0; static constexpr float INVS2 = 16.0f; };
template<> struct SP<3>  { static constexpr int SI = 1; static constexpr float INVS2 = 1.77777778f; };
template<> struct SP<8>  { static constexpr int SI = 2; static constexpr float INVS2 = 0.326530612f; };
template<> struct SP<18> { static constexpr int SI = 3; static constexpr float INVS2 = 0.0711111111f; };

// exact fp16 bit pattern for small non-negative integers (n <= 2048), duplicated.
struct TapArr { unsigned int v[64]; };
template<int L, int WID>
__host__ __device__ constexpr TapArr mk_taps() {
    TapArr t{};
    for (int j = 0; j < L; ++j) {
        int n = (j - WID) * (j - WID);
        unsigned short h = 0;
        if (n > 0) {
            int hb = 0;
            for (int i = 0; i < 12; ++i) if ((n >> i) & 1) hb = i;
            unsigned short mant = (unsigned short)((((unsigned)(n - (1 << hb))) << 10) >> hb);
            h = (unsigned short)(((15 + hb) << 10) | mant);
        }
        t.v[j] = (unsigned)h | ((unsigned)h << 16);
    }
    return t;
}

// All stages run max-chains on packed half2:
//  s1: in x fp32 -> u=(v,-v);  acc=(vc1, -vo1)           taps -a
//  s2: in (vc1,-vo1) direct;   acc=(vc2, -vo2)           taps -a
//  s3: in (vc2,-vo2), u=-in;   acc=(-vc3, vo3)           taps -a*c
//  s4: in (-vc3,vo3) direct;   acc=(-vc4, vo4) -> blend  taps -a*c
template<int WID, int STAGE, int BH>
__global__ __launch_bounds__(128)
void morph(const __half2* __restrict__ in, __half2* __restrict__ out,
           const float* __restrict__ x,
           const float* __restrict__ coef, const float* __restrict__ cmul,
           const float* __restrict__ alpha, float* __restrict__ outF)
{
    constexpr int  L = 2 * WID + 1;
    constexpr int  P = 2 * WID;
    constexpr int  M = BH + L - 1;     // inputs per block along morph axis
    constexpr int  CH = 16;            // pipeline chunk (MLP)
    constexpr int NM = (STAGE == 1) ? (Hn + P) : (STAGE == 2) ? (Wn + P)
                     : (STAGE == 3) ? Hn : Wn;
    constexpr int NL = (STAGE == 1) ? Wn : (STAGE == 2) ? (Hn + P)
                     : (STAGE == 3) ? (Wn + P) : Hn;
    constexpr TapArr TT = mk_taps<L, WID>();

    const int lane = threadIdx.x & 31;
    const int warp = threadIdx.x >> 5;
    const int b    = blockIdx.z;
    const int line = blockIdx.y * 4 + warp;
    const int a0   = blockIdx.x * BH;
    if (line >= NL) return;

    float af = coef[lane] * SP<WID>::INVS2;
    if (STAGE >= 3) af *= cmul[lane];
    const __half2 ah2 = __float2half2_rn(-af);

    const __half2 NINF = __halves2half2(__ushort_as_half(0xFC00), __ushort_as_half(0xFC00));
    __half2 acc[BH];
#pragma unroll
    for (int p = 0; p < BH; ++p) acc[p] = NINF;

    auto tap = [&](__half2 u, int m) {
#pragma unroll
        for (int p = 0; p < BH; ++p) {
            int j = m - p;
            if (j < 0 || j >= L) continue;
            unsigned int tb = TT.v[j];
            __half2 dj = *reinterpret_cast<const __half2*>(&tb);
            acc[p] = __hmax2(acc[p], __hfma2(dj, ah2, u));
        }
    };

    // ---- software-pipelined load/compute, double-buffered register chunks ----
    if constexpr (STAGE == 1) {
        const float* px = x + ((b * Hn * Wn + line) * Sn + SP<WID>::SI) * Cn + lane;
        constexpr int RS = Wn * Sn * Cn;
        const bool interior = (a0 >= P) && (a0 + M - 1 - P <= Hn - 1);
        float u[2][CH];
        auto ld = [&](int m) -> float {
            if (interior) return __ldg(px + (a0 + m - P) * RS);
            int xh = min(max(a0 + m - P, 0), Hn - 1);
            return __ldg(px + xh * RS);
        };
#pragma unroll
        for (int q = 0; q < CH; ++q) if (q < M) u[0][q] = ld(q);
#pragma unroll
        for (int m0 = 0; m0 < M; m0 += CH) {
            const int cur = (m0 / CH) & 1;
#pragma unroll
            for (int q = 0; q < CH; ++q)
                if (m0 + CH + q < M) u[cur ^ 1][q] = ld(m0 + CH + q);
#pragma unroll
            for (int q = 0; q < CH; ++q)
                if (m0 + q < M) {
                    float v = u[cur][q];
                    tap(__floats2half2_rn(v, -v), m0 + q);
                }
        }
    } else {
        // scratch-reading stages: uniform pipelined body over a strided pointer
        const __half2* p0;
        int ms;
        if constexpr (STAGE == 2) {
            p0 = in + (b * (Hn + P) + line) * (Wn * Cn) + lane;
            ms = Cn;
        } else if constexpr (STAGE == 3) {
            p0 = in + ((b * (Hn + P) + a0) * (Wn + P) + line) * Cn + lane;
            ms = (Wn + P) * Cn;
        } else {
            p0 = in + ((b * Hn + line) * (Wn + P) + a0) * Cn + lane;
            ms = Cn;
        }
        const bool interior2 = (STAGE != 2) ||
            ((a0 >= P) && (a0 + M - 1 - P <= Wn - 1));
        __half2 u[2][CH];
        auto ld = [&](int m) -> __half2 {
            if constexpr (STAGE == 2) {
                if (interior2) return __ldg(p0 + (a0 - P + m) * Cn);
                int cidx = min(max(a0 + m - P, 0), Wn - 1);
                return __ldg(p0 + cidx * Cn);
            } else {
                return __ldg(p0 + m * ms);
            }
        };
#pragma unroll
        for (int q = 0; q < CH; ++q) if (q < M) u[0][q] = ld(q);
#pragma unroll
        for (int m0 = 0; m0 < M; m0 += CH) {
            const int cur = (m0 / CH) & 1;
#pragma unroll
            for (int q = 0; q < CH; ++q)
                if (m0 + CH + q < M) u[cur ^ 1][q] = ld(m0 + CH + q);
#pragma unroll
            for (int q = 0; q < CH; ++q)
                if (m0 + q < M) {
                    __half2 v = u[cur][q];
                    if constexpr (STAGE == 3) v = __hneg2(v);
                    tap(v, m0 + q);
                }
        }
    }

    if constexpr (STAGE == 4) {
        float al = alpha[lane];
#pragma unroll
        for (int p = 0; p < BH; ++p) {
            float vc = -__low2float(acc[p]);
            float vo =  __high2float(acc[p]);
            float r  = fmaf(al, vc - vo, vo);   // alpha*xc + (1-alpha)*xo
            outF[(((b * Hn + line) * Wn + (a0 + p)) * Sn + SP<WID>::SI) * Cn + lane] = r;
        }
    } else if constexpr (STAGE == 1) {   // rows Hn+P x cols Wn — GUARDED
        const int base = ((b * (Hn + P) + a0) * Wn + line) * Cn + lane;
#pragma unroll
        for (int p = 0; p < BH; ++p) {
            if (a0 + p >= NM) continue;
            out[base + p * (Wn * Cn)] = acc[p];
        }
    } else if constexpr (STAGE == 2) {   // rows Hn+P x cols Wn+P — GUARDED
        const int base = ((b * (Hn + P) + line) * (Wn + P) + a0) * Cn + lane;
#pragma unroll
        for (int p = 0; p < BH; ++p) {
            if (a0 + p >= NM) continue;
            out[base + p * Cn] = acc[p];
        }
    } else {                              // stage 3: rows Hn (exact tiles)
        const int base = ((b * Hn + a0) * (Wn + P) + line) * Cn + lane;
#pragma unroll
        for (int p = 0; p < BH; ++p) out[base + p * ((Wn + P) * Cn)] = acc[p];
    }
}

static inline int cdiv(int a, int b) { return (a + b - 1) / b; }

template<int WID>
static void run_scale(const float* x, const float* coef, const float* cm,
                      const float* al, float* out, __half2* g1, __half2* g2,
                      cudaStream_t st)
{
    constexpr int BH = 16;
    constexpr int P = 2 * WID;
    morph<WID, 1, BH><<<dim3(cdiv(Hn + P, BH), cdiv(Wn, 4),     Bn), 128, 0, st>>>(
        nullptr, g1, x, coef, cm, al, nullptr);
    morph<WID, 2, BH><<<dim3(cdiv(Wn + P, BH), cdiv(Hn + P, 4), Bn), 128, 0, st>>>(
        g1, g2, nullptr, coef, cm, al, nullptr);
    morph<WID, 3, BH><<<dim3(cdiv(Hn, BH),     cdiv(Wn + P, 4), Bn), 128, 0, st>>>(
        g2, g1, nullptr, coef, cm, al, nullptr);
    morph<WID, 4, BH><<<dim3(cdiv(Wn, BH),     cdiv(Hn, 4),     Bn), 128, 0, st>>>(
        g1, nullptr, nullptr, coef, cm, al, out);
}

extern "C" void kernel_launch(void* const* d_in, const int* in_sizes, int n_in,
                              void* d_out, int out_size)
{
    const float* x    = (const float*)d_in[0];
    const float* coef = (const float*)d_in[1];
    const float* cm   = (const float*)d_in[2];
    const float* al   = (const float*)d_in[3];
    float* out = (float*)d_out;

    __half2 *a1, *a2, *b1, *b2;
    cudaGetSymbolAddress((void**)&a1, g_A1);
    cudaGetSymbolAddress((void**)&a2, g_A2);
    cudaGetSymbolAddress((void**)&b1, g_B1);
    cudaGetSymbolAddress((void**)&b2, g_B2);

    static cudaStream_t sB = nullptr;
    static cudaEvent_t evF = nullptr, evJ = nullptr;
    if (!sB) {
        cudaStreamCreateWithFlags(&sB, cudaStreamNonBlocking);
        cudaEventCreateWithFlags(&evF, cudaEventDisableTiming);
        cudaEventCreateWithFlags(&evJ, cudaEventDisableTiming);
    }

    cudaEventRecord(evF, 0);
    cudaStreamWaitEvent(sB, evF, 0);

    // A: w18 + w1 ; B: w8 + w3
    run_scale<8> (x, coef, cm, al, out, b1, b2, sB);
    run_scale<3> (x, coef, cm, al, out, b1, b2, sB);
    run_scale<18>(x, coef, cm, al, out, a1, a2, (cudaStream_t)0);
    run_scale<1> (x, coef, cm, al, out, a1, a2, (cudaStream_t)0);

    cudaEventRecord(evJ, sB);
    cudaStreamWaitEvent((cudaStream_t)0, evJ, 0);
}